// round 5
// baseline (speedup 1.0000x reference)
#include <cuda_runtime.h>
#include <cuda_bf16.h>
#include <cstdint>

#define B_    64
#define V_    2048
#define ENC_  128
#define T_    100
#define EMB_  256
#define DEC_  512
#define ATT_  256
#define VOC_  29
#define XDIM_ 896   // EMB + ENC + DEC
#define NROW_ 413   // 256 dec_att + 128 gate + 29 pred

// ---------------- scratch ----------------
__device__ __nv_bfloat16 g_enc_att_bf[(size_t)B_ * V_ * ATT_];   // 67 MB
__device__ __nv_bfloat16 g_enc_bf[(size_t)B_ * V_ * ENC_];       // 33.5 MB
__device__ float g_mean[B_ * ENC_];
__device__ float g_h[B_ * DEC_];     // masked h (carry)
__device__ float g_hn[B_ * DEC_];    // raw h_new (for pred)
__device__ float g_c[B_ * DEC_];
__device__ float g_dec_att[B_ * ATT_];
__device__ float g_gate[B_ * ENC_];
__device__ float g_scores[B_ * V_];
__device__ float g_x[B_ * XDIM_];                      // [emb | gated awe | h]
__device__ float g_gates_p[2][B_ * 4 * DEC_];          // split-K partials
__device__ float g_awe_p[B_ * 4 * ENC_];               // per-chunk awe partials
__device__ unsigned int g_cnt[B_];                     // zero-init; wraps each step

__device__ __forceinline__ float sigm(float x) { return 1.0f / (1.0f + __expf(-x)); }

// ---------------- enc -> bf16 copy (once) ----------------
__global__ void k_enc_bf(const float* __restrict__ enc) {
    size_t i = (size_t)blockIdx.x * blockDim.x + threadIdx.x;
    const float4* in = (const float4*)enc;
    float4 v = in[i];
    __nv_bfloat162* out = (__nv_bfloat162*)g_enc_bf;
    out[i * 2]     = __floats2bfloat162_rn(v.x, v.y);
    out[i * 2 + 1] = __floats2bfloat162_rn(v.z, v.w);
}

// ---------------- enc_att (once) ----------------
__global__ void k_enc_att(const float* __restrict__ enc,
                          const float* __restrict__ W_enc,
                          const float* __restrict__ b_enc) {
    extern __shared__ float sm[];
    float* sWT = sm;                 // [128][257]
    float* sE  = sm + 128 * 257;     // [16][128]
    int tid = threadIdx.x;
    for (int idx = tid; idx < ATT_ * ENC_; idx += 256) {
        int a = idx >> 7, e = idx & 127;
        sWT[e * 257 + a] = W_enc[idx];
    }
    int row0 = blockIdx.x * 16;
    for (int idx = tid; idx < 16 * ENC_; idx += 256) {
        int r = idx >> 7, e = idx & 127;
        sE[r * ENC_ + e] = enc[(size_t)(row0 + r) * ENC_ + e];
    }
    __syncthreads();
    int a = tid;
    float bb = b_enc[a];
    float acc[16];
#pragma unroll
    for (int r = 0; r < 16; r++) acc[r] = bb;
    for (int e = 0; e < ENC_; e++) {
        float w = sWT[e * 257 + a];
#pragma unroll
        for (int r = 0; r < 16; r++) acc[r] = fmaf(sE[r * ENC_ + e], w, acc[r]);
    }
#pragma unroll
    for (int r = 0; r < 16; r++)
        g_enc_att_bf[(size_t)(row0 + r) * ATT_ + a] = __float2bfloat16(acc[r]);
}

// ---------------- mean over V (once) ----------------
__global__ void k_mean(const float* __restrict__ enc) {
    int b = blockIdx.x, tid = threadIdx.x;
    int g = tid >> 7, e = tid & 127;
    const float* base = enc + ((size_t)b * V_ + g * 512) * ENC_ + e;
    float s = 0.f;
#pragma unroll 8
    for (int v = 0; v < 512; v++) s += base[(size_t)v * ENC_];
    __shared__ float sp[4][128];
    sp[g][e] = s;
    __syncthreads();
    if (tid < 128)
        g_mean[b * ENC_ + tid] = (sp[0][tid] + sp[1][tid] + sp[2][tid] + sp[3][tid]) * (1.0f / V_);
}

// dec_att + gate from h in smem (init only)
__device__ __forceinline__ void attention_pre(int b, int tid, const float* sh,
                                              const float* __restrict__ W_dec,
                                              const float* __restrict__ b_dec,
                                              const float* __restrict__ W_beta,
                                              const float* __restrict__ b_beta) {
    const float4* h4 = (const float4*)sh;
    if (tid < ATT_) {
        float acc = b_dec[tid];
        const float4* w = (const float4*)(W_dec + tid * DEC_);
#pragma unroll 8
        for (int k = 0; k < DEC_ / 4; k++) {
            float4 a = w[k]; float4 h = h4[k];
            acc += a.x * h.x + a.y * h.y + a.z * h.z + a.w * h.w;
        }
        g_dec_att[b * ATT_ + tid] = acc;
    } else if (tid < ATT_ + ENC_) {
        int e = tid - ATT_;
        float acc = b_beta[e];
        const float4* w = (const float4*)(W_beta + e * DEC_);
#pragma unroll 8
        for (int k = 0; k < DEC_ / 4; k++) {
            float4 a = w[k]; float4 h = h4[k];
            acc += a.x * h.x + a.y * h.y + a.z * h.z + a.w * h.w;
        }
        g_gate[b * ENC_ + e] = sigm(acc);
    }
}

// ---------------- h0/c0 + first dec_att/gate + emb(0) ----------------
__global__ void k_init(const float* __restrict__ Wh, const float* __restrict__ bh,
                       const float* __restrict__ Wc, const float* __restrict__ bc,
                       const float* __restrict__ W_dec, const float* __restrict__ b_dec,
                       const float* __restrict__ W_beta, const float* __restrict__ b_beta,
                       const int* __restrict__ caps, const float* __restrict__ emb_W) {
    int b = blockIdx.x, tid = threadIdx.x;
    __shared__ float smn[ENC_];
    __shared__ float sh[DEC_];
    if (tid < ENC_) smn[tid] = g_mean[b * ENC_ + tid];
    __syncthreads();
    {
        int d = tid;
        float ah = bh[d], ac = bc[d];
        const float4* wrh = (const float4*)(Wh + d * ENC_);
        const float4* wrc = (const float4*)(Wc + d * ENC_);
        const float4* mv  = (const float4*)smn;
#pragma unroll 8
        for (int k = 0; k < ENC_ / 4; k++) {
            float4 m4 = mv[k]; float4 h4 = wrh[k]; float4 c4 = wrc[k];
            ah += m4.x * h4.x + m4.y * h4.y + m4.z * h4.z + m4.w * h4.w;
            ac += m4.x * c4.x + m4.y * c4.y + m4.z * c4.z + m4.w * c4.w;
        }
        g_h[b * DEC_ + d] = ah;
        g_c[b * DEC_ + d] = ac;
        g_x[b * XDIM_ + EMB_ + ENC_ + d] = ah;
        sh[d] = ah;
    }
    if (tid < 256) {
        int cap = caps[b * T_];
        g_x[b * XDIM_ + tid] = emb_W[cap * EMB_ + tid];
    }
    __syncthreads();
    attention_pre(b, tid, sh, W_dec, b_dec, W_beta, b_beta);
}

// ---------------- scores = relu(enc_att + dec_att) @ w_full + b_full ----------------
__global__ void k_scores(const float* __restrict__ w_full, const float* __restrict__ b_full) {
    int b = blockIdx.x >> 6;
    int v0 = (blockIdx.x & 63) * 32;
    __shared__ float sda[ATT_], sw[ATT_];
    int tid = threadIdx.x;
    sda[tid] = g_dec_att[b * ATT_ + tid];
    sw[tid]  = w_full[tid];
    __syncthreads();
    int warp = tid >> 5, lane = tid & 31;
    float bf = b_full[0];
#pragma unroll
    for (int i = 0; i < 4; i++) {
        int v = v0 + warp * 4 + i;
        const __nv_bfloat162* row =
            (const __nv_bfloat162*)(g_enc_att_bf + (size_t)(b * V_ + v) * ATT_);
        float acc = 0.f;
#pragma unroll
        for (int k = 0; k < 4; k++) {
            int a2 = lane + k * 32;
            float2 e2 = __bfloat1622float2(row[a2]);
            int a = a2 * 2;
            acc += fmaxf(e2.x + sda[a], 0.f) * sw[a]
                 + fmaxf(e2.y + sda[a + 1], 0.f) * sw[a + 1];
        }
#pragma unroll
        for (int o = 16; o; o >>= 1) acc += __shfl_xor_sync(0xFFFFFFFFu, acc, o);
        if (lane == 0) g_scores[b * V_ + v] = acc + bf;
    }
}

// ---------------- softmax + alpha-out + partial awe; last CTA per b reduces ----------------
// grid (64, 4), 512 threads. Chunk g covers voxels [g*512, (g+1)*512).
__global__ void k_smax(const int* __restrict__ lens, float* __restrict__ out_alpha, int t) {
    int b = blockIdx.x, g = blockIdx.y, tid = threadIdx.x;
    __shared__ float s_al[512];
    __shared__ float red[16];
    __shared__ float part[4][128];
    __shared__ bool isLast;

    float sc[4];
#pragma unroll
    for (int i = 0; i < 4; i++) sc[i] = g_scores[b * V_ + tid + i * 512];
    float mx = fmaxf(fmaxf(sc[0], sc[1]), fmaxf(sc[2], sc[3]));
#pragma unroll
    for (int o = 16; o; o >>= 1) mx = fmaxf(mx, __shfl_xor_sync(0xFFFFFFFFu, mx, o));
    if ((tid & 31) == 0) red[tid >> 5] = mx;
    __syncthreads();
    if (tid == 0) {
        float m2 = red[0];
#pragma unroll
        for (int i = 1; i < 16; i++) m2 = fmaxf(m2, red[i]);
        red[0] = m2;
    }
    __syncthreads();
    mx = red[0];
    float se = 0.f;
#pragma unroll
    for (int i = 0; i < 4; i++) { sc[i] = __expf(sc[i] - mx); se += sc[i]; }
#pragma unroll
    for (int o = 16; o; o >>= 1) se += __shfl_xor_sync(0xFFFFFFFFu, se, o);
    __syncthreads();
    if ((tid & 31) == 0) red[tid >> 5] = se;
    __syncthreads();
    if (tid == 0) {
        float s = 0.f;
#pragma unroll
        for (int i = 0; i < 16; i++) s += red[i];
        red[0] = s;
    }
    __syncthreads();
    float inv = 1.0f / red[0];
    bool m = t < lens[b];
    float al = sc[g] * inv;                       // this thread's voxel in own chunk
    out_alpha[(size_t)(b * T_ + t) * V_ + g * 512 + tid] = m ? al : 0.f;
    s_al[tid] = al;
    __syncthreads();

    // partial awe over this chunk's 512 voxels
    int sub = tid >> 7, e = tid & 127;
    const __nv_bfloat16* base = g_enc_bf + ((size_t)b * V_ + g * 512 + sub * 128) * ENC_ + e;
    const float* ap = s_al + sub * 128;
    float s = 0.f;
#pragma unroll 8
    for (int v = 0; v < 128; v++) s += ap[v] * __bfloat162float(base[(size_t)v * ENC_]);
    part[sub][e] = s;
    __syncthreads();
    if (tid < 128)
        g_awe_p[(b * 4 + g) * ENC_ + tid] =
            part[0][tid] + part[1][tid] + part[2][tid] + part[3][tid];

    __threadfence();
    __syncthreads();
    if (tid == 0) {
        unsigned int v = atomicInc(&g_cnt[b], 3u);   // wraps to 0 after the 4th
        isLast = (v == 3u);
    }
    __syncthreads();
    if (isLast && tid < 128) {
        float tot = g_awe_p[(b * 4 + 0) * ENC_ + tid] + g_awe_p[(b * 4 + 1) * ENC_ + tid]
                  + g_awe_p[(b * 4 + 2) * ENC_ + tid] + g_awe_p[(b * 4 + 3) * ENC_ + tid];
        g_x[b * XDIM_ + EMB_ + tid] = tot * g_gate[b * ENC_ + tid];
    }
}

// ---------------- split-K gates GEMM ----------------
__global__ void k_gemm(const float* __restrict__ W_ih, const float* __restrict__ W_hh) {
    int slab = blockIdx.y;
    int j0 = blockIdx.x * 16;
    __shared__ float sX[64 * 33];
    __shared__ float sW[32 * 16];
    int tid = threadIdx.x;
    int jj = tid & 15, bq = tid >> 4;
    const float* src = slab ? W_hh : W_ih;
    int ld   = slab ? DEC_ : 384;
    int kx0  = slab ? 384 : 0;
    int nch  = slab ? 16 : 12;
    float acc[4] = {0.f, 0.f, 0.f, 0.f};
    for (int kc = 0; kc < nch; kc++) {
        int k0 = kc * 32;
#pragma unroll
        for (int r = 0; r < 8; r++) {
            int idx = tid + r * 256;
            int bb = idx >> 5, kk = idx & 31;
            sX[bb * 33 + kk] = g_x[bb * XDIM_ + kx0 + k0 + kk];
        }
#pragma unroll
        for (int r = 0; r < 2; r++) {
            int e = tid + r * 256;
            int j2 = e >> 5, kk = e & 31;
            sW[kk * 16 + j2] = src[(j0 + j2) * ld + k0 + kk];
        }
        __syncthreads();
#pragma unroll
        for (int kk = 0; kk < 32; kk++) {
            float w = sW[kk * 16 + jj];
#pragma unroll
            for (int i = 0; i < 4; i++)
                acc[i] = fmaf(sX[(bq * 4 + i) * 33 + kk], w, acc[i]);
        }
        __syncthreads();
    }
    int j = j0 + jj;
#pragma unroll
    for (int i = 0; i < 4; i++)
        g_gates_p[slab][(bq * 4 + i) * (4 * DEC_) + j] = acc[i];
}

// ---------------- LSTM cell (elementwise) + emb prefetch for t+1 ----------------
__global__ void k_cell(const int* __restrict__ lens,
                       const float* __restrict__ b_ih, const float* __restrict__ b_hh,
                       const int* __restrict__ caps, const float* __restrict__ emb_W, int t) {
    int b = blockIdx.x, tid = threadIdx.x;
    int base = b * 4 * DEC_;
    float gi = g_gates_p[0][base + tid]            + g_gates_p[1][base + tid]
             + b_ih[tid]            + b_hh[tid];
    float gf = g_gates_p[0][base + DEC_ + tid]     + g_gates_p[1][base + DEC_ + tid]
             + b_ih[DEC_ + tid]     + b_hh[DEC_ + tid];
    float gg = g_gates_p[0][base + 2 * DEC_ + tid] + g_gates_p[1][base + 2 * DEC_ + tid]
             + b_ih[2 * DEC_ + tid] + b_hh[2 * DEC_ + tid];
    float go = g_gates_p[0][base + 3 * DEC_ + tid] + g_gates_p[1][base + 3 * DEC_ + tid]
             + b_ih[3 * DEC_ + tid] + b_hh[3 * DEC_ + tid];
    float ig = sigm(gi), fg = sigm(gf), og = sigm(go);
    float gt = tanhf(gg);
    float c_old = g_c[b * DEC_ + tid];
    float cn = fg * c_old + ig * gt;
    float hn = og * tanhf(cn);
    bool m = t < lens[b];
    float h_old = g_h[b * DEC_ + tid];
    float h2 = m ? hn : h_old;
    float c2 = m ? cn : c_old;
    g_h[b * DEC_ + tid] = h2;
    g_c[b * DEC_ + tid] = c2;
    g_hn[b * DEC_ + tid] = hn;
    g_x[b * XDIM_ + EMB_ + ENC_ + tid] = h2;
    if (tid < 256 && t + 1 < T_) {
        int cap = caps[b * T_ + t + 1];
        g_x[b * XDIM_ + tid] = emb_W[cap * EMB_ + tid];
    }
}

// ---------------- pre: dec_att / gate / pred as [413 x 512] @ [512 x 64] ----------------
// grid 26 CTAs x 16 rows, 256 threads: jj=row-in-CTA, q=b-quad (4 b each).
__global__ void k_pre(const float* __restrict__ W_dec, const float* __restrict__ b_dec,
                      const float* __restrict__ W_beta, const float* __restrict__ b_beta,
                      const float* __restrict__ W_final, const float* __restrict__ b_final,
                      const int* __restrict__ lens, float* __restrict__ out_pred, int t) {
    int tid = threadIdx.x;
    int j = blockIdx.x * 16 + (tid >> 4);
    int q = tid & 15;
    if (j >= NROW_) return;
    const float* W; float bias; int mode;
    if (j < 256)      { W = W_dec   + j * DEC_;          bias = b_dec[j];        mode = 0; }
    else if (j < 384) { W = W_beta  + (j - 256) * DEC_;  bias = b_beta[j - 256]; mode = 1; }
    else              { W = W_final + (j - 384) * DEC_;  bias = b_final[j - 384];mode = 2; }
    const float* H = (mode == 2) ? g_hn : g_h;
    int b0 = q * 4;
    const float4* w4 = (const float4*)W;
    const float4* h0 = (const float4*)(H + (b0 + 0) * DEC_);
    const float4* h1 = (const float4*)(H + (b0 + 1) * DEC_);
    const float4* h2 = (const float4*)(H + (b0 + 2) * DEC_);
    const float4* h3 = (const float4*)(H + (b0 + 3) * DEC_);
    float a0 = 0.f, a1 = 0.f, a2 = 0.f, a3 = 0.f;
#pragma unroll 8
    for (int k = 0; k < DEC_ / 4; k++) {
        float4 w = w4[k];
        float4 x0 = h0[k], x1 = h1[k], x2 = h2[k], x3 = h3[k];
        a0 += w.x * x0.x + w.y * x0.y + w.z * x0.z + w.w * x0.w;
        a1 += w.x * x1.x + w.y * x1.y + w.z * x1.z + w.w * x1.w;
        a2 += w.x * x2.x + w.y * x2.y + w.z * x2.z + w.w * x2.w;
        a3 += w.x * x3.x + w.y * x3.y + w.z * x3.z + w.w * x3.w;
    }
    float r[4] = {a0 + bias, a1 + bias, a2 + bias, a3 + bias};
#pragma unroll
    for (int i = 0; i < 4; i++) {
        int b = b0 + i;
        if (mode == 0)      g_dec_att[b * ATT_ + j] = r[i];
        else if (mode == 1) g_gate[b * ENC_ + (j - 256)] = sigm(r[i]);
        else out_pred[(size_t)(b * T_ + t) * VOC_ + (j - 384)] = (t < lens[b]) ? r[i] : 0.f;
    }
}

__global__ void k_lens(const int* __restrict__ lens, float* __restrict__ out) {
    int i = threadIdx.x;
    if (i < B_) out[i] = (float)lens[i];
}

// ---------------- launch ----------------
extern "C" void kernel_launch(void* const* d_in, const int* in_sizes, int n_in,
                              void* d_out, int out_size) {
    const float* enc      = (const float*)d_in[0];
    const int*   caps     = (const int*)  d_in[1];
    const int*   lens     = (const int*)  d_in[2];
    const float* emb_W    = (const float*)d_in[3];
    const float* W_enc    = (const float*)d_in[4];
    const float* b_enc    = (const float*)d_in[5];
    const float* W_dec    = (const float*)d_in[6];
    const float* b_dec    = (const float*)d_in[7];
    const float* w_full   = (const float*)d_in[8];
    const float* b_full   = (const float*)d_in[9];
    const float* W_ih     = (const float*)d_in[10];
    const float* b_ih     = (const float*)d_in[11];
    const float* W_hh     = (const float*)d_in[12];
    const float* b_hh     = (const float*)d_in[13];
    const float* W_init_h = (const float*)d_in[14];
    const float* b_init_h = (const float*)d_in[15];
    const float* W_init_c = (const float*)d_in[16];
    const float* b_init_c = (const float*)d_in[17];
    const float* W_beta   = (const float*)d_in[18];
    const float* b_beta   = (const float*)d_in[19];
    const float* W_final  = (const float*)d_in[20];
    const float* b_final  = (const float*)d_in[21];

    float* out       = (float*)d_out;
    float* out_pred  = out;                                    // [B,T,VOC]
    float* out_alpha = out + (size_t)B_ * T_ * VOC_;           // [B,T,V]
    float* out_lens  = out_alpha + (size_t)B_ * T_ * V_;       // [B]

    const int SMEM_EA = (128 * 257 + 16 * 128) * 4;
    static bool attr_done = false;
    if (!attr_done) {
        cudaFuncSetAttribute(k_enc_att, cudaFuncAttributeMaxDynamicSharedMemorySize, SMEM_EA);
        attr_done = true;
    }

    k_enc_bf<<<(B_ * V_ * ENC_) / 4 / 256, 256>>>(enc);
    k_enc_att<<<(B_ * V_) / 16, 256, SMEM_EA>>>(enc, W_enc, b_enc);
    k_mean<<<B_, 512>>>(enc);
    k_init<<<B_, 512>>>(W_init_h, b_init_h, W_init_c, b_init_c,
                        W_dec, b_dec, W_beta, b_beta, caps, emb_W);
    for (int t = 0; t < T_; t++) {
        k_scores<<<4096, 256>>>(w_full, b_full);
        k_smax<<<dim3(B_, 4), 512>>>(lens, out_alpha, t);
        dim3 gg(128, 2);
        k_gemm<<<gg, 256>>>(W_ih, W_hh);
        k_cell<<<B_, 512>>>(lens, b_ih, b_hh, caps, emb_W, t);
        k_pre<<<26, 256>>>(W_dec, b_dec, W_beta, b_beta, W_final, b_final,
                           lens, out_pred, t);
    }
    k_lens<<<1, 64>>>(lens, out_lens);
}

// round 6
// speedup vs baseline: 1.4404x; 1.4404x over previous
#include <cuda_runtime.h>
#include <cuda_bf16.h>
#include <cstdint>

#define B_    64
#define V_    2048
#define ENC_  128
#define T_    100
#define EMB_  256
#define DEC_  512
#define ATT_  256
#define VOC_  29
#define XDIM_ 896   // EMB + ENC + DEC
#define NROW_ 413   // 256 dec_att + 128 gate + 29 pred

#define GRID_ 148
#define NTHR_ 1024
#define NBAR_ 512

// ---------------- scratch ----------------
__device__ __nv_bfloat16 g_enc_att_bf[(size_t)B_ * V_ * ATT_];   // 67 MB
__device__ __nv_bfloat16 g_enc_bf[(size_t)B_ * V_ * ENC_];       // 33.5 MB
__device__ float g_mean[B_ * ENC_];
__device__ float g_h[B_ * DEC_];     // masked h (carry)
__device__ float g_hn[B_ * DEC_];    // raw h_new (for pred)
__device__ float g_c[B_ * DEC_];
__device__ float g_dec_att[B_ * ATT_];
__device__ float g_gate[B_ * ENC_];
__device__ float g_scores[B_ * V_];
__device__ float g_x[B_ * XDIM_];                      // [emb | gated awe | h]
__device__ float g_gates_p[2][B_ * 4 * DEC_];          // split-K partials
__device__ float g_awe_p[B_ * 4 * ENC_];               // per-chunk awe partials
__device__ unsigned g_cnt[B_];                         // wraps each step
__device__ unsigned g_bar_slots[NBAR_];                // zeroed by k_reset each run

__device__ __forceinline__ float sigm(float x) { return 1.0f / (1.0f + __expf(-x)); }

// grid-wide barrier, one slot per use
__device__ __forceinline__ void gridbar(int slot) {
    __syncthreads();
    if (threadIdx.x == 0) {
        __threadfence();                         // release (drains, CCTL.IVALL)
        unsigned* p = &g_bar_slots[slot];
        unsigned v = atomicAdd(p, 1u) + 1u;
        if (v < GRID_) {
            unsigned cur; long long guard = 0;
            do {
                asm volatile("ld.acquire.gpu.u32 %0, [%1];" : "=r"(cur) : "l"(p));
                if (cur >= GRID_) break;
                __nanosleep(32);
            } while (++guard < (1LL << 31));
        }
        __threadfence();                         // acquire + L1 invalidate
    }
    __syncthreads();
}

// ---------------- prologue kernels (run once, outside the loop) ----------------
__global__ void k_enc_bf(const float* __restrict__ enc) {
    size_t i = (size_t)blockIdx.x * blockDim.x + threadIdx.x;
    const float4* in = (const float4*)enc;
    float4 v = in[i];
    __nv_bfloat162* out = (__nv_bfloat162*)g_enc_bf;
    out[i * 2]     = __floats2bfloat162_rn(v.x, v.y);
    out[i * 2 + 1] = __floats2bfloat162_rn(v.z, v.w);
}

__global__ void k_enc_att(const float* __restrict__ enc,
                          const float* __restrict__ W_enc,
                          const float* __restrict__ b_enc) {
    extern __shared__ float sm[];
    float* sWT = sm;                 // [128][257]
    float* sE  = sm + 128 * 257;     // [16][128]
    int tid = threadIdx.x;
    for (int idx = tid; idx < ATT_ * ENC_; idx += 256) {
        int a = idx >> 7, e = idx & 127;
        sWT[e * 257 + a] = W_enc[idx];
    }
    int row0 = blockIdx.x * 16;
    for (int idx = tid; idx < 16 * ENC_; idx += 256) {
        int r = idx >> 7, e = idx & 127;
        sE[r * ENC_ + e] = enc[(size_t)(row0 + r) * ENC_ + e];
    }
    __syncthreads();
    int a = tid;
    float bb = b_enc[a];
    float acc[16];
#pragma unroll
    for (int r = 0; r < 16; r++) acc[r] = bb;
    for (int e = 0; e < ENC_; e++) {
        float w = sWT[e * 257 + a];
#pragma unroll
        for (int r = 0; r < 16; r++) acc[r] = fmaf(sE[r * ENC_ + e], w, acc[r]);
    }
#pragma unroll
    for (int r = 0; r < 16; r++)
        g_enc_att_bf[(size_t)(row0 + r) * ATT_ + a] = __float2bfloat16(acc[r]);
}

__global__ void k_mean(const float* __restrict__ enc) {
    int b = blockIdx.x, tid = threadIdx.x;
    int g = tid >> 7, e = tid & 127;
    const float* base = enc + ((size_t)b * V_ + g * 512) * ENC_ + e;
    float s = 0.f;
#pragma unroll 8
    for (int v = 0; v < 512; v++) s += base[(size_t)v * ENC_];
    __shared__ float sp[4][128];
    sp[g][e] = s;
    __syncthreads();
    if (tid < 128)
        g_mean[b * ENC_ + tid] = (sp[0][tid] + sp[1][tid] + sp[2][tid] + sp[3][tid]) * (1.0f / V_);
}

__device__ __forceinline__ void attention_pre(int b, int tid, const float* sh,
                                              const float* __restrict__ W_dec,
                                              const float* __restrict__ b_dec,
                                              const float* __restrict__ W_beta,
                                              const float* __restrict__ b_beta) {
    const float4* h4 = (const float4*)sh;
    if (tid < ATT_) {
        float acc = b_dec[tid];
        const float4* w = (const float4*)(W_dec + tid * DEC_);
#pragma unroll 8
        for (int k = 0; k < DEC_ / 4; k++) {
            float4 a = w[k]; float4 h = h4[k];
            acc += a.x * h.x + a.y * h.y + a.z * h.z + a.w * h.w;
        }
        g_dec_att[b * ATT_ + tid] = acc;
    } else if (tid < ATT_ + ENC_) {
        int e = tid - ATT_;
        float acc = b_beta[e];
        const float4* w = (const float4*)(W_beta + e * DEC_);
#pragma unroll 8
        for (int k = 0; k < DEC_ / 4; k++) {
            float4 a = w[k]; float4 h = h4[k];
            acc += a.x * h.x + a.y * h.y + a.z * h.z + a.w * h.w;
        }
        g_gate[b * ENC_ + e] = sigm(acc);
    }
}

__global__ void k_init(const float* __restrict__ Wh, const float* __restrict__ bh,
                       const float* __restrict__ Wc, const float* __restrict__ bc,
                       const float* __restrict__ W_dec, const float* __restrict__ b_dec,
                       const float* __restrict__ W_beta, const float* __restrict__ b_beta,
                       const int* __restrict__ caps, const float* __restrict__ emb_W) {
    int b = blockIdx.x, tid = threadIdx.x;
    __shared__ float smn[ENC_];
    __shared__ float sh[DEC_];
    if (tid < ENC_) smn[tid] = g_mean[b * ENC_ + tid];
    __syncthreads();
    {
        int d = tid;
        float ah = bh[d], ac = bc[d];
        const float4* wrh = (const float4*)(Wh + d * ENC_);
        const float4* wrc = (const float4*)(Wc + d * ENC_);
        const float4* mv  = (const float4*)smn;
#pragma unroll 8
        for (int k = 0; k < ENC_ / 4; k++) {
            float4 m4 = mv[k]; float4 h4 = wrh[k]; float4 c4 = wrc[k];
            ah += m4.x * h4.x + m4.y * h4.y + m4.z * h4.z + m4.w * h4.w;
            ac += m4.x * c4.x + m4.y * c4.y + m4.z * c4.z + m4.w * c4.w;
        }
        g_h[b * DEC_ + d] = ah;
        g_c[b * DEC_ + d] = ac;
        g_x[b * XDIM_ + EMB_ + ENC_ + d] = ah;
        sh[d] = ah;
    }
    if (tid < 256) {
        int cap = caps[b * T_];
        g_x[b * XDIM_ + tid] = emb_W[cap * EMB_ + tid];
    }
    __syncthreads();
    attention_pre(b, tid, sh, W_dec, b_dec, W_beta, b_beta);
}

// ---------------- the persistent loop kernel ----------------
__global__ void __launch_bounds__(NTHR_, 1)
k_loop(const int* __restrict__ lens, const int* __restrict__ caps,
       const float* __restrict__ emb_W,
       const float* __restrict__ w_full, const float* __restrict__ b_full,
       const float* __restrict__ W_ih, const float* __restrict__ W_hh,
       const float* __restrict__ b_ih, const float* __restrict__ b_hh,
       const float* __restrict__ W_dec, const float* __restrict__ b_dec,
       const float* __restrict__ W_beta, const float* __restrict__ b_beta,
       const float* __restrict__ W_final, const float* __restrict__ b_final,
       float* __restrict__ out_pred, float* __restrict__ out_alpha)
{
    extern __shared__ float sm[];
    __shared__ unsigned sflag;
    const int cta = blockIdx.x, tid = threadIdx.x;
    const int warp = tid >> 5, lane = tid & 31;
    int bs = 0;

    for (int t = 0; t < T_; t++) {
        // ===== Phase A: scores = relu(enc_att + dec_att) @ w_full + b_full =====
        {
            float* sda = sm;           // [256]
            float* sw  = sm + 256;     // [256]
            for (int task = cta; task < 512; task += GRID_) {
                int b = task >> 3;
                int v0 = (task & 7) * 256;
                __syncthreads();
                if (tid < 256) sda[tid] = g_dec_att[b * ATT_ + tid];
                else if (tid < 512) sw[tid - 256] = w_full[tid - 256];
                __syncthreads();
                float bf = b_full[0];
#pragma unroll
                for (int r = 0; r < 8; r++) {
                    int v = v0 + warp * 8 + r;
                    const __nv_bfloat162* row =
                        (const __nv_bfloat162*)(g_enc_att_bf + (size_t)(b * V_ + v) * ATT_);
                    float acc = 0.f;
#pragma unroll
                    for (int k = 0; k < 4; k++) {
                        int a2 = lane + k * 32;
                        float2 e2 = __bfloat1622float2(row[a2]);
                        int a = a2 * 2;
                        acc += fmaxf(e2.x + sda[a], 0.f) * sw[a]
                             + fmaxf(e2.y + sda[a + 1], 0.f) * sw[a + 1];
                    }
#pragma unroll
                    for (int o = 16; o; o >>= 1) acc += __shfl_xor_sync(0xFFFFFFFFu, acc, o);
                    if (lane == 0) g_scores[b * V_ + v] = acc + bf;
                }
            }
        }
        gridbar(bs++);

        // ===== Phase B: softmax + alpha out + awe partials (+last-CTA combine) =====
        {
            float* s_al = sm;            // [512]
            float* red  = sm + 512;      // [32]
            float* part = sm + 544;      // [8][128]
            for (int task = cta; task < 256; task += GRID_) {
                int b = task >> 2, g = task & 3;
                __syncthreads();
                float sc0 = g_scores[b * V_ + tid];
                float sc1 = g_scores[b * V_ + tid + 1024];
                float mx = fmaxf(sc0, sc1);
#pragma unroll
                for (int o = 16; o; o >>= 1) mx = fmaxf(mx, __shfl_xor_sync(0xFFFFFFFFu, mx, o));
                if (lane == 0) red[warp] = mx;
                __syncthreads();
                if (tid < 32) {
                    float m2 = red[tid];
#pragma unroll
                    for (int o = 16; o; o >>= 1) m2 = fmaxf(m2, __shfl_xor_sync(0xFFFFFFFFu, m2, o));
                    if (tid == 0) red[0] = m2;
                }
                __syncthreads();
                mx = red[0];
                float e0 = __expf(sc0 - mx), e1 = __expf(sc1 - mx);
                float se = e0 + e1;
#pragma unroll
                for (int o = 16; o; o >>= 1) se += __shfl_xor_sync(0xFFFFFFFFu, se, o);
                __syncthreads();
                if (lane == 0) red[warp] = se;
                __syncthreads();
                if (tid < 32) {
                    float s2 = red[tid];
#pragma unroll
                    for (int o = 16; o; o >>= 1) s2 += __shfl_xor_sync(0xFFFFFFFFu, s2, o);
                    if (tid == 0) red[0] = s2;
                }
                __syncthreads();
                float inv = 1.0f / red[0];
                bool msk = t < lens[b];
                // this chunk's 512 voxels: v = g*512 + sv
                int half = g & 1;                 // 0: tid<512 owns, 1: tid>=512 owns
                int i_sel = g >> 1;               // which of (sc0, sc1)
                int owner = (tid >> 9) == half;
                if (owner) {
                    int sv = tid - half * 512;
                    float ex = i_sel ? e1 : e0;
                    float al = ex * inv;
                    s_al[sv] = al;
                    out_alpha[(size_t)(b * T_ + t) * V_ + g * 512 + sv] = msk ? al : 0.f;
                }
                __syncthreads();
                // partial awe over this chunk
                int sub = tid >> 7, e = tid & 127;
                const __nv_bfloat16* base =
                    g_enc_bf + ((size_t)b * V_ + g * 512 + sub * 64) * ENC_ + e;
                const float* ap = s_al + sub * 64;
                float s = 0.f;
#pragma unroll 8
                for (int v = 0; v < 64; v++) s += ap[v] * __bfloat162float(base[(size_t)v * ENC_]);
                part[sub * 128 + e] = s;
                __syncthreads();
                if (tid < 128) {
                    float tot = 0.f;
#pragma unroll
                    for (int k = 0; k < 8; k++) tot += part[k * 128 + tid];
                    g_awe_p[(b * 4 + g) * ENC_ + tid] = tot;
                }
                __threadfence();
                __syncthreads();
                if (tid == 0) {
                    unsigned v = atomicInc(&g_cnt[b], 3u);
                    sflag = (v == 3u);
                }
                __syncthreads();
                if (sflag) {
                    __threadfence();   // see other CTAs' partials
                    if (tid < 128) {
                        float tot = g_awe_p[(b * 4 + 0) * ENC_ + tid]
                                  + g_awe_p[(b * 4 + 1) * ENC_ + tid]
                                  + g_awe_p[(b * 4 + 2) * ENC_ + tid]
                                  + g_awe_p[(b * 4 + 3) * ENC_ + tid];
                        g_x[b * XDIM_ + EMB_ + tid] = tot * g_gate[b * ENC_ + tid];
                    }
                }
            }
        }
        gridbar(bs++);

        // ===== Phase C: gates GEMM, tasks = (jt 0..127, slab 0..1) =====
        {
            float* sX  = sm;                       // [64][132]
            float* sW  = sm + 64 * 132;            // [16][133]
            float* red = sW + 16 * 133;            // [4096]
            int jj = tid & 15, bq = (tid >> 4) & 15, ks = tid >> 8;
            for (int task = cta; task < 256; task += GRID_) {
                int slab = task >> 7;
                int j0 = (task & 127) * 16;
                const float* src = slab ? W_hh : W_ih;
                int ld  = slab ? DEC_ : 384;
                int kx0 = slab ? 384 : 0;
                int nch = slab ? 4 : 3;
                float acc[4] = {0.f, 0.f, 0.f, 0.f};
                for (int kc = 0; kc < nch; kc++) {
                    int k0 = kc * 128;
                    __syncthreads();
#pragma unroll
                    for (int r = 0; r < 8; r++) {
                        int idx = tid + r * 1024;
                        int bb = idx >> 7, kk = idx & 127;
                        sX[bb * 132 + kk] = g_x[bb * XDIM_ + kx0 + k0 + kk];
                    }
#pragma unroll
                    for (int r = 0; r < 2; r++) {
                        int e2 = tid + r * 1024;
                        int j2 = e2 >> 7, kk = e2 & 127;
                        sW[j2 * 133 + kk] = src[(j0 + j2) * ld + k0 + kk];
                    }
                    __syncthreads();
                    const float* wrow = sW + jj * 133 + ks * 32;
#pragma unroll
                    for (int kk = 0; kk < 32; kk++) {
                        float w = wrow[kk];
#pragma unroll
                        for (int i = 0; i < 4; i++)
                            acc[i] = fmaf(sX[(bq * 4 + i) * 132 + ks * 32 + kk], w, acc[i]);
                    }
                }
                __syncthreads();
#pragma unroll
                for (int i = 0; i < 4; i++)
                    red[(ks * 256 + bq * 16 + jj) * 4 + i] = acc[i];
                __syncthreads();
                {
                    int jr = tid & 15, br = (tid >> 4) & 15, ir = tid >> 8;
                    float s = red[(0 * 256 + br * 16 + jr) * 4 + ir]
                            + red[(1 * 256 + br * 16 + jr) * 4 + ir]
                            + red[(2 * 256 + br * 16 + jr) * 4 + ir]
                            + red[(3 * 256 + br * 16 + jr) * 4 + ir];
                    int b = br * 4 + ir;
                    g_gates_p[slab][b * (4 * DEC_) + j0 + jr] = s;
                }
            }
        }
        gridbar(bs++);

        // ===== Phase D: LSTM cell (elementwise) + emb prefetch =====
        if (cta < B_) {
            int b = cta;
            if (tid < DEC_) {
                int base = b * 4 * DEC_;
                float gi = g_gates_p[0][base + tid]            + g_gates_p[1][base + tid]
                         + b_ih[tid]            + b_hh[tid];
                float gf = g_gates_p[0][base + DEC_ + tid]     + g_gates_p[1][base + DEC_ + tid]
                         + b_ih[DEC_ + tid]     + b_hh[DEC_ + tid];
                float gg = g_gates_p[0][base + 2 * DEC_ + tid] + g_gates_p[1][base + 2 * DEC_ + tid]
                         + b_ih[2 * DEC_ + tid] + b_hh[2 * DEC_ + tid];
                float go = g_gates_p[0][base + 3 * DEC_ + tid] + g_gates_p[1][base + 3 * DEC_ + tid]
                         + b_ih[3 * DEC_ + tid] + b_hh[3 * DEC_ + tid];
                float ig = sigm(gi), fg = sigm(gf), og = sigm(go);
                float gt = tanhf(gg);
                float c_old = g_c[b * DEC_ + tid];
                float cn = fg * c_old + ig * gt;
                float hn = og * tanhf(cn);
                bool msk = t < lens[b];
                float h_old = g_h[b * DEC_ + tid];
                float h2 = msk ? hn : h_old;
                float c2 = msk ? cn : c_old;
                g_h[b * DEC_ + tid] = h2;
                g_c[b * DEC_ + tid] = c2;
                g_hn[b * DEC_ + tid] = hn;
                g_x[b * XDIM_ + EMB_ + ENC_ + tid] = h2;
            } else if (tid < DEC_ + EMB_ && t + 1 < T_) {
                int e = tid - DEC_;
                int cap = caps[b * T_ + t + 1];
                g_x[b * XDIM_ + e] = emb_W[cap * EMB_ + e];
            }
        }
        gridbar(bs++);

        // ===== Phase E: dec_att / gate / pred — [413x512] @ h, tasks of 4 rows =====
        {
            float* red = sm;                 // [4 rr][4 ks][64 b]
            int rr = tid >> 8, ks = (tid >> 6) & 3, b = tid & 63;
            for (int task = cta; task < 104; task += GRID_) {
                int r0 = task * 4;
                int j = r0 + rr;
                float acc = 0.f;
                __syncthreads();
                if (j < NROW_) {
                    const float* W;
                    if (j < 256)      W = W_dec   + j * DEC_;
                    else if (j < 384) W = W_beta  + (j - 256) * DEC_;
                    else              W = W_final + (j - 384) * DEC_;
                    const float* H = (j < 384) ? g_h : g_hn;
                    const float4* w4 = (const float4*)(W) + ks * 32;
                    const float4* h4 = (const float4*)(H + b * DEC_) + ks * 32;
#pragma unroll 8
                    for (int k = 0; k < 32; k++) {
                        float4 w = w4[k]; float4 x = h4[k];
                        acc += w.x * x.x + w.y * x.y + w.z * x.z + w.w * x.w;
                    }
                }
                red[(rr * 4 + ks) * 64 + b] = acc;
                __syncthreads();
                if (tid < 256) {
                    int rr2 = tid >> 6, b2 = tid & 63;
                    int j2 = r0 + rr2;
                    if (j2 < NROW_) {
                        float s = red[(rr2 * 4 + 0) * 64 + b2] + red[(rr2 * 4 + 1) * 64 + b2]
                                + red[(rr2 * 4 + 2) * 64 + b2] + red[(rr2 * 4 + 3) * 64 + b2];
                        if (j2 < 256)
                            g_dec_att[b2 * ATT_ + j2] = s + b_dec[j2];
                        else if (j2 < 384)
                            g_gate[b2 * ENC_ + (j2 - 256)] = sigm(s + b_beta[j2 - 256]);
                        else {
                            bool msk = t < lens[b2];
                            out_pred[(size_t)(b2 * T_ + t) * VOC_ + (j2 - 384)] =
                                msk ? (s + b_final[j2 - 384]) : 0.f;
                        }
                    }
                }
            }
        }
        gridbar(bs++);
    }
}

__global__ void k_reset(const int* __restrict__ lens, float* __restrict__ out_lens) {
    int i = threadIdx.x;
    if (i < NBAR_) g_bar_slots[i] = 0;
    if (i < B_) { g_cnt[i] = 0; out_lens[i] = (float)lens[i]; }
}

// ---------------- launch ----------------
extern "C" void kernel_launch(void* const* d_in, const int* in_sizes, int n_in,
                              void* d_out, int out_size) {
    const float* enc      = (const float*)d_in[0];
    const int*   caps     = (const int*)  d_in[1];
    const int*   lens     = (const int*)  d_in[2];
    const float* emb_W    = (const float*)d_in[3];
    const float* W_enc    = (const float*)d_in[4];
    const float* b_enc    = (const float*)d_in[5];
    const float* W_dec    = (const float*)d_in[6];
    const float* b_dec    = (const float*)d_in[7];
    const float* w_full   = (const float*)d_in[8];
    const float* b_full   = (const float*)d_in[9];
    const float* W_ih     = (const float*)d_in[10];
    const float* b_ih     = (const float*)d_in[11];
    const float* W_hh     = (const float*)d_in[12];
    const float* b_hh     = (const float*)d_in[13];
    const float* W_init_h = (const float*)d_in[14];
    const float* b_init_h = (const float*)d_in[15];
    const float* W_init_c = (const float*)d_in[16];
    const float* b_init_c = (const float*)d_in[17];
    const float* W_beta   = (const float*)d_in[18];
    const float* b_beta   = (const float*)d_in[19];
    const float* W_final  = (const float*)d_in[20];
    const float* b_final  = (const float*)d_in[21];

    float* out       = (float*)d_out;
    float* out_pred  = out;                                    // [B,T,VOC]
    float* out_alpha = out + (size_t)B_ * T_ * VOC_;           // [B,T,V]
    float* out_lens  = out_alpha + (size_t)B_ * T_ * V_;       // [B]

    const int SMEM_EA   = (128 * 257 + 16 * 128) * 4;          // 139776 B
    const int SMEM_LOOP = (64 * 132 + 16 * 133 + 4096) * 4;    // 58688 B
    static bool attr_done = false;
    if (!attr_done) {
        cudaFuncSetAttribute(k_enc_att, cudaFuncAttributeMaxDynamicSharedMemorySize, SMEM_EA);
        cudaFuncSetAttribute(k_loop, cudaFuncAttributeMaxDynamicSharedMemorySize, SMEM_LOOP);
        attr_done = true;
    }

    k_enc_bf<<<(B_ * V_ * ENC_) / 4 / 256, 256>>>(enc);
    k_enc_att<<<(B_ * V_) / 16, 256, SMEM_EA>>>(enc, W_enc, b_enc);
    k_mean<<<B_, 512>>>(enc);
    k_init<<<B_, 512>>>(W_init_h, b_init_h, W_init_c, b_init_c,
                        W_dec, b_dec, W_beta, b_beta, caps, emb_W);
    k_loop<<<GRID_, NTHR_, SMEM_LOOP>>>(lens, caps, emb_W, w_full, b_full,
                                        W_ih, W_hh, b_ih, b_hh,
                                        W_dec, b_dec, W_beta, b_beta,
                                        W_final, b_final, out_pred, out_alpha);
    k_reset<<<1, NBAR_>>>(lens, out_lens);
}